// round 14
// baseline (speedup 1.0000x reference)
#include <cuda_runtime.h>
#include <cuda_fp16.h>
#include <cstdint>

// LSTM B=8192, T=128, I=32, H=64, OUT=8.
// R13: R7 math (fp16 m16n8k16, fp32 tanh.approx act, frag-major LDS.128,
// 2-group interleaved pipeline) at 512 threads: 16 warps, each owning
// M=16 rows x 8 gate-cols (per gate). 4 warps/SMSP lets the arbiter overlap
// tensor-stalled warps with MUFU-issuing warps.

#define B_TOT 8192
#define T_LEN 128
#define I_SZ  32
#define H_SZ  64
#define OUT_SZ 8
#define M_BLK 64
#define NTHREADS 512

__device__ __forceinline__ uint32_t packh2(float a, float b) {
    __half2 h = __floats2half2_rn(a, b);   // .x = a (low)
    return *reinterpret_cast<uint32_t*>(&h);
}
__device__ __forceinline__ float tanhhw(float x) {
    float y;
    asm("tanh.approx.f32 %0, %1;" : "=f"(y) : "f"(x));
    return y;
}
__device__ __forceinline__ void mma_f16(float c[4],
                                        uint32_t a0, uint32_t a1, uint32_t a2, uint32_t a3,
                                        uint32_t b0, uint32_t b1) {
    asm("mma.sync.aligned.m16n8k16.row.col.f32.f16.f16.f32 "
        "{%0,%1,%2,%3},{%4,%5,%6,%7},{%8,%9},{%0,%1,%2,%3};"
        : "+f"(c[0]), "+f"(c[1]), "+f"(c[2]), "+f"(c[3])
        : "r"(a0), "r"(a1), "r"(a2), "r"(a3), "r"(b0), "r"(b1));
}

// one q-slice (16 rows x k16): LDS.128 + 4 gate MMAs
__device__ __forceinline__ void frag_mma(float acc[4][4], const uint32_t* __restrict__ blk,
                                         int lane, const uint32_t (&bfr)[4][6][2], int q) {
    uint4 av = *reinterpret_cast<const uint4*>(blk + lane * 4);
    #pragma unroll
    for (int g = 0; g < 4; ++g)
        mma_f16(acc[g], av.x, av.y, av.z, av.w, bfr[g][q][0], bfr[g][q][1]);
}

// activate 4 elems (this thread's m16n8 tile); i/f/o pre-scaled by 0.5
__device__ __forceinline__ void act_r(const float acc[4][4], float cst[4], float hv[4]) {
    #pragma unroll
    for (int e = 0; e < 4; ++e) {
        float ig = fmaf(tanhhw(acc[0][e]), 0.5f, 0.5f);
        float fg = fmaf(tanhhw(acc[1][e]), 0.5f, 0.5f);
        float gg = tanhhw(acc[2][e]);
        float og = fmaf(tanhhw(acc[3][e]), 0.5f, 0.5f);
        float c  = fg * cst[e] + ig * gg;
        cst[e] = c;
        hv[e] = og * tanhhw(c);
    }
}

// Phase: mma(group GM) into accM; act(accA -> h of group GA); stage x(GA,t+1).
template <int GM, int GA>
__device__ __forceinline__ void phase_fn(uint32_t* __restrict__ Xs, uint32_t* __restrict__ Hs,
                                         float (&accM)[4][4], float (&accA)[4][4],
                                         float* cst, float2& xr,
                                         const float* __restrict__ xga, int t,
                                         int lane, int rb, int xoff, int hoff,
                                         const uint32_t (&bfr)[4][6][2],
                                         const float (&bias2)[4][2]) {
    const uint32_t* Xm = Xs + GM * 512;
    const uint32_t* Hm = Hs + GM * 1024;

    #pragma unroll
    for (int g = 0; g < 4; ++g) {
        accM[g][0] = bias2[g][0];
        accM[g][1] = bias2[g][1];
        accM[g][2] = bias2[g][0];
        accM[g][3] = bias2[g][1];
    }

    float hv[4];
    act_r(accA, cst, hv);   // MUFU stream up front; HMMA stream follows

    frag_mma(accM, Xm + (0 * 2 + rb) * 128, lane, bfr, 0);
    frag_mma(accM, Xm + (1 * 2 + rb) * 128, lane, bfr, 1);
    frag_mma(accM, Hm + (0 * 2 + rb) * 128, lane, bfr, 2);
    frag_mma(accM, Hm + (1 * 2 + rb) * 128, lane, bfr, 3);

    // stage x(GA, t+1) + prefetch x(GA, t+2)  (one half2 word per thread)
    {
        uint32_t* Xa = Xs + GA * 512;
        Xa[xoff] = packh2(xr.x, xr.y);
        int tt = (t + 2 < T_LEN) ? t + 2 : T_LEN - 1;
        xr = *reinterpret_cast<const float2*>(xga + (size_t)tt * I_SZ);
    }

    frag_mma(accM, Hm + (2 * 2 + rb) * 128, lane, bfr, 4);

    // h(GA) writeback: one STS.64 (rows arl / arl+8 of this warp's 16-row block)
    {
        uint32_t* Ha = Hs + GA * 1024;
        *reinterpret_cast<uint2*>(Ha + hoff) =
            make_uint2(packh2(hv[0], hv[1]), packh2(hv[2], hv[3]));
    }

    frag_mma(accM, Hm + (3 * 2 + rb) * 128, lane, bfr, 5);
}

__global__ __launch_bounds__(NTHREADS, 1)
void lstm_fp16_kernel(const float* __restrict__ x,
                      const float* __restrict__ W_ih,
                      const float* __restrict__ W_hh,
                      const float* __restrict__ b_ih,
                      const float* __restrict__ b_hh,
                      const float* __restrict__ W_fc,
                      const float* __restrict__ b_fc,
                      float* __restrict__ out) {
    __shared__ __align__(16) uint32_t Xs[2 * 512];
    __shared__ __align__(16) uint32_t Hs[2 * 1024];

    const int tid  = threadIdx.x;
    const int warp = tid >> 5;
    const int lane = tid & 31;
    const int row0 = blockIdx.x * M_BLK;
    const int cw   = warp >> 1;        // column-slice 0..7
    const int rb   = warp & 1;         // 16-row block within the 32-row group
    const int colw = cw * 8;
    const int arl  = lane >> 2;
    const int akl  = lane & 3;

    // ---- B fragments (fp16 half2), i/f/o pre-scaled by 0.5 ----
    uint32_t bfr[4][6][2];
    float bias2[4][2];
    {
        const int gc_base = colw + arl;
        #pragma unroll
        for (int g = 0; g < 4; ++g) {
            const int gc = g * 64 + gc_base;
            const float s = (g == 2) ? 1.0f : 0.5f;
            #pragma unroll
            for (int q = 0; q < 6; ++q) {
                const int k0 = q * 16 + 2 * akl;
                float w[4];
                #pragma unroll
                for (int j = 0; j < 4; ++j) {
                    const int k = k0 + ((j < 2) ? j : j + 6);   // k0,k0+1,k0+8,k0+9
                    w[j] = (k < I_SZ) ? W_ih[gc * I_SZ + k] : W_hh[gc * H_SZ + (k - I_SZ)];
                }
                bfr[g][q][0] = packh2(w[0] * s, w[1] * s);
                bfr[g][q][1] = packh2(w[2] * s, w[3] * s);
            }
            const int c0 = g * 64 + colw + 2 * akl;
            bias2[g][0] = (b_ih[c0] + b_hh[c0]) * s;
            bias2[g][1] = (b_ih[c0 + 1] + b_hh[c0 + 1]) * s;
        }
    }

    // zero H tiles (h0 = 0)
    for (int i = tid; i < 2 * 1024; i += NTHREADS) Hs[i] = 0u;

    // h writeback offset: h-col block qh = cw>>1, half = cw&1, row block rb
    const int hoff = ((cw >> 1) * 2 + rb) * 128 + lane * 4 + 2 * (cw & 1);

    // ---- x staging: one float2 (-> one half2 word) per thread per group ----
    const int srow  = tid >> 4;          // 0..31
    const int scol2 = (tid & 15) * 2;    // 0..30
    int xoff;
    {
        const int qx = scol2 >> 4, rx = srow >> 4;
        const int arls = srow & 7, subx = (srow >> 3) & 1;
        const int p = (scol2 & 15) >> 1;
        xoff = (qx * 2 + rx) * 128 + (arls * 4 + (p & 3)) * 4 + subx + 2 * (p >> 2);
    }
    const float* xga0 = x + ((size_t)(row0 + srow) * T_LEN) * I_SZ + scol2;
    const float* xga1 = x + ((size_t)(row0 + 32 + srow) * T_LEN) * I_SZ + scol2;

    float2 xr0, xr1;
    {
        float2 v0 = *reinterpret_cast<const float2*>(xga0);
        float2 v1 = *reinterpret_cast<const float2*>(xga1);
        Xs[xoff]       = packh2(v0.x, v0.y);
        Xs[512 + xoff] = packh2(v1.x, v1.y);
        xr0 = *reinterpret_cast<const float2*>(xga0 + I_SZ);
        xr1 = *reinterpret_cast<const float2*>(xga1 + I_SZ);
    }

    float acc0[4][4], acc1[4][4];
    float cst0[4] = {}, cst1[4] = {};

    __syncthreads();

    // prologue: gates(G0, 0) -> acc0
    {
        #pragma unroll
        for (int g = 0; g < 4; ++g) {
            acc0[g][0] = bias2[g][0];
            acc0[g][1] = bias2[g][1];
            acc0[g][2] = bias2[g][0];
            acc0[g][3] = bias2[g][1];
        }
        frag_mma(acc0, Xs + (0 * 2 + rb) * 128, lane, bfr, 0);
        frag_mma(acc0, Xs + (1 * 2 + rb) * 128, lane, bfr, 1);
        #pragma unroll
        for (int qh = 0; qh < 4; ++qh)
            frag_mma(acc0, Hs + (qh * 2 + rb) * 128, lane, bfr, 2 + qh);
    }
    __syncthreads();

    for (int t = 0; t < T_LEN; ++t) {
        phase_fn<1, 0>(Xs, Hs, acc1, acc0, cst0, xr0, xga0, t,
                       lane, rb, xoff, hoff, bfr, bias2);
        __syncthreads();
        phase_fn<0, 1>(Xs, Hs, acc0, acc1, cst1, xr1, xga1, t,
                       lane, rb, xoff, hoff, bfr, bias2);
        __syncthreads();
    }

    // ---- FC epilogue: gather h_T from frag-major fp16 tiles ----
    for (int idx = tid; idx < M_BLK * OUT_SZ; idx += NTHREADS) {
        const int row = idx >> 3;
        const int o   = idx & 7;
        const int g   = row >> 5;
        const int lr  = row & 31;
        const int r   = lr >> 4, arle = lr & 7, sube = (lr >> 3) & 1;
        const uint32_t* Hg = Hs + g * 1024;
        const float* wf = W_fc + o * H_SZ;
        float s = b_fc[o];
        #pragma unroll
        for (int cc = 0; cc < 32; ++cc) {
            const int c  = cc * 2;
            const int qh = c >> 4;
            const int p  = (c & 15) >> 1;
            uint32_t wv = Hg[(qh * 2 + r) * 128 + (arle * 4 + (p & 3)) * 4 + sube + 2 * (p >> 2)];
            __half2 h2 = *reinterpret_cast<__half2*>(&wv);
            float2 f2 = __half22float2(h2);
            s += f2.x * wf[c] + f2.y * wf[c + 1];
        }
        out[(size_t)(row0 + row) * OUT_SZ + o] = s;
    }
}

extern "C" void kernel_launch(void* const* d_in, const int* in_sizes, int n_in,
                              void* d_out, int out_size) {
    const float* x    = (const float*)d_in[0];
    const float* W_ih = (const float*)d_in[1];
    const float* W_hh = (const float*)d_in[2];
    const float* b_ih = (const float*)d_in[3];
    const float* b_hh = (const float*)d_in[4];
    const float* W_fc = (const float*)d_in[5];
    const float* b_fc = (const float*)d_in[6];
    float* out = (float*)d_out;

    lstm_fp16_kernel<<<B_TOT / M_BLK, NTHREADS>>>(x, W_ih, W_hh, b_ih, b_hh, W_fc, b_fc, out);
}

// round 15
// speedup vs baseline: 1.6062x; 1.6062x over previous
#include <cuda_runtime.h>
#include <cuda_fp16.h>
#include <cstdint>

// LSTM B=8192, T=128, I=32, H=64, OUT=8.
// R15 = R7 (fp16 m16n8k16, frag-major LDS.128, 2-group interleaved pipeline,
// fp32 tanh.approx, 256 threads, weights register-resident) + warp-role
// staggering: warps 0-3 run act->mma, warps 4-7 run mma->act, so the two
// warps sharing each SMSP feed MUFU and TENSOR pipes concurrently.

#define B_TOT 8192
#define T_LEN 128
#define I_SZ  32
#define H_SZ  64
#define OUT_SZ 8
#define M_BLK 64
#define NTHREADS 256

__device__ __forceinline__ uint32_t packh2(float a, float b) {
    __half2 h = __floats2half2_rn(a, b);   // .x = a (low)
    return *reinterpret_cast<uint32_t*>(&h);
}
__device__ __forceinline__ float tanhhw(float x) {
    float y;
    asm("tanh.approx.f32 %0, %1;" : "=f"(y) : "f"(x));
    return y;
}
__device__ __forceinline__ void mma_f16(float c[4],
                                        uint32_t a0, uint32_t a1, uint32_t a2, uint32_t a3,
                                        uint32_t b0, uint32_t b1) {
    asm("mma.sync.aligned.m16n8k16.row.col.f32.f16.f16.f32 "
        "{%0,%1,%2,%3},{%4,%5,%6,%7},{%8,%9},{%0,%1,%2,%3};"
        : "+f"(c[0]), "+f"(c[1]), "+f"(c[2]), "+f"(c[3])
        : "r"(a0), "r"(a1), "r"(a2), "r"(a3), "r"(b0), "r"(b1));
}

// one (q, r) fragment: LDS.128 + 4 gate MMAs
__device__ __forceinline__ void frag_mma(float accr[4][4], const uint32_t* __restrict__ blk,
                                         int lane, const uint32_t (&bfr)[4][6][2], int q) {
    uint4 av = *reinterpret_cast<const uint4*>(blk + lane * 4);
    #pragma unroll
    for (int g = 0; g < 4; ++g)
        mma_f16(accr[g], av.x, av.y, av.z, av.w, bfr[g][q][0], bfr[g][q][1]);
}

// activate 4 elems; i/f/o accs pre-scaled by 0.5 (sigmoid = 0.5*tanh+0.5)
__device__ __forceinline__ void act_r(const float acc[4][4], float cst[4], float hv[4]) {
    #pragma unroll
    for (int e = 0; e < 4; ++e) {
        float ig = fmaf(tanhhw(acc[0][e]), 0.5f, 0.5f);
        float fg = fmaf(tanhhw(acc[1][e]), 0.5f, 0.5f);
        float gg = tanhhw(acc[2][e]);
        float og = fmaf(tanhhw(acc[3][e]), 0.5f, 0.5f);
        float c  = fg * cst[e] + ig * gg;
        cst[e] = c;
        hv[e] = og * tanhhw(c);
    }
}

__device__ __forceinline__ void mma12(float (&accM)[2][4][4],
                                      const uint32_t* __restrict__ Xm,
                                      const uint32_t* __restrict__ Hm,
                                      int lane, const uint32_t (&bfr)[4][6][2]) {
    frag_mma(accM[0], Xm + 0,   lane, bfr, 0);
    frag_mma(accM[1], Xm + 128, lane, bfr, 0);
    frag_mma(accM[0], Xm + 256, lane, bfr, 1);
    frag_mma(accM[1], Xm + 384, lane, bfr, 1);
    frag_mma(accM[0], Hm + 0,   lane, bfr, 2);
    frag_mma(accM[1], Hm + 128, lane, bfr, 2);
    frag_mma(accM[0], Hm + 256, lane, bfr, 3);
    frag_mma(accM[1], Hm + 384, lane, bfr, 3);
    frag_mma(accM[0], Hm + 512, lane, bfr, 4);
    frag_mma(accM[1], Hm + 640, lane, bfr, 4);
    frag_mma(accM[0], Hm + 768, lane, bfr, 5);
    frag_mma(accM[1], Hm + 896, lane, bfr, 5);
}

// Phase: mma(group GM) into accM; act(accA -> h of group GA); stage x(GA,t+1).
// act_first staggers the per-warp order so SMSP siblings feed different pipes.
template <int GM, int GA>
__device__ __forceinline__ void phase_fn(uint32_t* __restrict__ Xs, uint32_t* __restrict__ Hs,
                                         float (&accM)[2][4][4], float (&accA)[2][4][4],
                                         float (&cst)[2][4], float4& xr,
                                         const float* __restrict__ xga, int t, int lane,
                                         bool act_first,
                                         int xoff0, int xoff1, int hoff0, int hoff1,
                                         const uint32_t (&bfr)[4][6][2],
                                         const float (&bias2)[4][2]) {
    const uint32_t* Xm = Xs + GM * 512;
    const uint32_t* Hm = Hs + GM * 1024;

    #pragma unroll
    for (int r = 0; r < 2; ++r)
        #pragma unroll
        for (int g = 0; g < 4; ++g) {
            accM[r][g][0] = bias2[g][0];
            accM[r][g][1] = bias2[g][1];
            accM[r][g][2] = bias2[g][0];
            accM[r][g][3] = bias2[g][1];
        }

    float hv0[4], hv1[4];

    if (act_first) {
        act_r(accA[0], cst[0], hv0);
        act_r(accA[1], cst[1], hv1);
        mma12(accM, Xm, Hm, lane, bfr);
    } else {
        mma12(accM, Xm, Hm, lane, bfr);
        act_r(accA[0], cst[0], hv0);
        act_r(accA[1], cst[1], hv1);
    }

    // stage x(GA, t+1) + prefetch x(GA, t+2)
    {
        uint32_t* Xa = Xs + GA * 512;
        Xa[xoff0] = packh2(xr.x, xr.y);
        Xa[xoff1] = packh2(xr.z, xr.w);
        int tt = (t + 2 < T_LEN) ? t + 2 : T_LEN - 1;
        xr = *reinterpret_cast<const float4*>(xga + (size_t)tt * I_SZ);
    }

    // h(GA) writeback: 2 x STS.64 into frag-major H tile
    {
        uint32_t* Ha = Hs + GA * 1024;
        *reinterpret_cast<uint2*>(Ha + hoff0) =
            make_uint2(packh2(hv0[0], hv0[1]), packh2(hv0[2], hv0[3]));
        *reinterpret_cast<uint2*>(Ha + hoff1) =
            make_uint2(packh2(hv1[0], hv1[1]), packh2(hv1[2], hv1[3]));
    }
}

__global__ __launch_bounds__(NTHREADS, 1)
void lstm_fp16_kernel(const float* __restrict__ x,
                      const float* __restrict__ W_ih,
                      const float* __restrict__ W_hh,
                      const float* __restrict__ b_ih,
                      const float* __restrict__ b_hh,
                      const float* __restrict__ W_fc,
                      const float* __restrict__ b_fc,
                      float* __restrict__ out) {
    __shared__ __align__(16) uint32_t Xs[2 * 512];
    __shared__ __align__(16) uint32_t Hs[2 * 1024];

    const int tid  = threadIdx.x;
    const int warp = tid >> 5;
    const int lane = tid & 31;
    const int row0 = blockIdx.x * M_BLK;
    const int colw = warp * 8;
    const int arl  = lane >> 2;
    const int akl  = lane & 3;
    const bool act_first = warp < 4;   // SMSP sibling (warp+4) runs mma-first

    // ---- B fragments (fp16 half2), i/f/o pre-scaled by 0.5 ----
    uint32_t bfr[4][6][2];
    float bias2[4][2];
    {
        const int gc_base = colw + arl;
        #pragma unroll
        for (int g = 0; g < 4; ++g) {
            const int gc = g * 64 + gc_base;
            const float s = (g == 2) ? 1.0f : 0.5f;
            #pragma unroll
            for (int q = 0; q < 6; ++q) {
                const int k0 = q * 16 + 2 * akl;
                float w[4];
                #pragma unroll
                for (int j = 0; j < 4; ++j) {
                    const int k = k0 + ((j < 2) ? j : j + 6);   // k0,k0+1,k0+8,k0+9
                    w[j] = (k < I_SZ) ? W_ih[gc * I_SZ + k] : W_hh[gc * H_SZ + (k - I_SZ)];
                }
                bfr[g][q][0] = packh2(w[0] * s, w[1] * s);
                bfr[g][q][1] = packh2(w[2] * s, w[3] * s);
            }
            const int c0 = g * 64 + colw + 2 * akl;
            bias2[g][0] = (b_ih[c0] + b_hh[c0]) * s;
            bias2[g][1] = (b_ih[c0 + 1] + b_hh[c0 + 1]) * s;
        }
    }

    // zero H tiles (h0 = 0)
    for (int i = tid; i < 2 * 1024; i += NTHREADS) Hs[i] = 0u;

    // ---- x staging ownership: float4 per thread per group ----
    const int srow = tid >> 3;
    const int scol = (tid & 7) * 4;
    int xoff0, xoff1;
    {
        const int qx = scol >> 4, rx = srow >> 4;
        const int arls = srow & 7, subx = (srow >> 3) & 1;
        const int p0 = (scol & 15) >> 1;
        const int tg0 = p0 & 3, hfx = p0 >> 2;
        const int word = subx + 2 * hfx;
        xoff0 = (qx * 2 + rx) * 128 + (arls * 4 + tg0) * 4 + word;
        xoff1 = xoff0 + 4;
    }
    const int hoff0 = ((warp >> 1) * 2) * 128 + lane * 4 + 2 * (warp & 1);
    const int hoff1 = hoff0 + 128;

    const float* xga0 = x + ((size_t)(row0 + srow) * T_LEN) * I_SZ + scol;
    const float* xga1 = x + ((size_t)(row0 + 32 + srow) * T_LEN) * I_SZ + scol;

    float4 xr0, xr1;
    {
        float4 v0 = *reinterpret_cast<const float4*>(xga0);
        float4 v1 = *reinterpret_cast<const float4*>(xga1);
        Xs[xoff0]       = packh2(v0.x, v0.y);
        Xs[xoff1]       = packh2(v0.z, v0.w);
        Xs[512 + xoff0] = packh2(v1.x, v1.y);
        Xs[512 + xoff1] = packh2(v1.z, v1.w);
        xr0 = *reinterpret_cast<const float4*>(xga0 + I_SZ);
        xr1 = *reinterpret_cast<const float4*>(xga1 + I_SZ);
    }

    float acc0[2][4][4], acc1[2][4][4];
    float cst0[2][4] = {}, cst1[2][4] = {};

    __syncthreads();

    // prologue: gates(G0, 0) -> acc0
    {
        #pragma unroll
        for (int r = 0; r < 2; ++r)
            #pragma unroll
            for (int g = 0; g < 4; ++g) {
                acc0[r][g][0] = bias2[g][0];
                acc0[r][g][1] = bias2[g][1];
                acc0[r][g][2] = bias2[g][0];
                acc0[r][g][3] = bias2[g][1];
            }
        mma12(acc0, Xs, Hs, lane, bfr);
    }
    __syncthreads();

    for (int t = 0; t < T_LEN; ++t) {
        phase_fn<1, 0>(Xs, Hs, acc1, acc0, cst0, xr0, xga0, t, lane, act_first,
                       xoff0, xoff1, hoff0, hoff1, bfr, bias2);
        __syncthreads();
        phase_fn<0, 1>(Xs, Hs, acc0, acc1, cst1, xr1, xga1, t, lane, act_first,
                       xoff0, xoff1, hoff0, hoff1, bfr, bias2);
        __syncthreads();
    }

    // ---- FC epilogue: gather h_T from frag-major fp16 tiles ----
    for (int idx = tid; idx < M_BLK * OUT_SZ; idx += NTHREADS) {
        const int row = idx >> 3;
        const int o   = idx & 7;
        const int g   = row >> 5;
        const int lr  = row & 31;
        const int r   = lr >> 4, arle = lr & 7, sube = (lr >> 3) & 1;
        const uint32_t* Hg = Hs + g * 1024;
        const float* wf = W_fc + o * H_SZ;
        float s = b_fc[o];
        #pragma unroll
        for (int cc = 0; cc < 32; ++cc) {
            const int c  = cc * 2;
            const int qh = c >> 4;
            const int p  = (c & 15) >> 1;
            uint32_t wv = Hg[(qh * 2 + r) * 128 + (arle * 4 + (p & 3)) * 4 + sube + 2 * (p >> 2)];
            __half2 h2 = *reinterpret_cast<__half2*>(&wv);
            float2 f2 = __half22float2(h2);
            s += f2.x * wf[c] + f2.y * wf[c + 1];
        }
        out[(size_t)(row0 + row) * OUT_SZ + o] = s;
    }
}

extern "C" void kernel_launch(void* const* d_in, const int* in_sizes, int n_in,
                              void* d_out, int out_size) {
    const float* x    = (const float*)d_in[0];
    const float* W_ih = (const float*)d_in[1];
    const float* W_hh = (const float*)d_in[2];
    const float* b_ih = (const float*)d_in[3];
    const float* b_hh = (const float*)d_in[4];
    const float* W_fc = (const float*)d_in[5];
    const float* b_fc = (const float*)d_in[6];
    float* out = (float*)d_out;

    lstm_fp16_kernel<<<B_TOT / M_BLK, NTHREADS>>>(x, W_ih, W_hh, b_ih, b_hh, W_fc, b_fc, out);
}

// round 16
// speedup vs baseline: 1.6965x; 1.0562x over previous
#include <cuda_runtime.h>
#include <cuda_fp16.h>
#include <cstdint>

// LSTM B=8192, T=128, I=32, H=64, OUT=8.
// R16 = R7 structure (frag-major LDS.128, 2-group interleaved pipeline,
// 256 threads, weights register-resident) with fp16-ACCUMULATE MMA
// (m16n8k16.f16.f16.f16.f16): gates are born packed half2, activations run
// entirely in the half2 domain (tanh.approx.f16x2 + HFMA2/HMUL2), h words
// store directly. Zero fp32<->fp16 cvts in the loop; MUFU halved.

#define B_TOT 8192
#define T_LEN 128
#define I_SZ  32
#define H_SZ  64
#define OUT_SZ 8
#define M_BLK 64
#define NTHREADS 256

__device__ __forceinline__ uint32_t packh2(float a, float b) {
    __half2 h = __floats2half2_rn(a, b);   // .x = a (low)
    return *reinterpret_cast<uint32_t*>(&h);
}
__device__ __forceinline__ __half2 u2h(uint32_t u) { return *reinterpret_cast<__half2*>(&u); }
__device__ __forceinline__ uint32_t h2u(__half2 h) { return *reinterpret_cast<uint32_t*>(&h); }

__device__ __forceinline__ uint32_t tanh2u(uint32_t u) {
    uint32_t v;
    asm("tanh.approx.f16x2 %0, %1;" : "=r"(v) : "r"(u));
    return v;
}
// fp16-accumulate MMA: acc = 2 packed half2 regs
__device__ __forceinline__ void mma_f16a(uint32_t c[2],
                                         uint32_t a0, uint32_t a1, uint32_t a2, uint32_t a3,
                                         uint32_t b0, uint32_t b1) {
    asm("mma.sync.aligned.m16n8k16.row.col.f16.f16.f16.f16 "
        "{%0,%1},{%2,%3,%4,%5},{%6,%7},{%0,%1};"
        : "+r"(c[0]), "+r"(c[1])
        : "r"(a0), "r"(a1), "r"(a2), "r"(a3), "r"(b0), "r"(b1));
}

// one (q, r) fragment: LDS.128 + 4 gate MMAs
__device__ __forceinline__ void frag_mma(uint32_t accr[4][2], const uint32_t* __restrict__ blk,
                                         int lane, const uint32_t (&bfr)[4][6][2], int q) {
    uint4 av = *reinterpret_cast<const uint4*>(blk + lane * 4);
    #pragma unroll
    for (int g = 0; g < 4; ++g)
        mma_f16a(accr[g], av.x, av.y, av.z, av.w, bfr[g][q][0], bfr[g][q][1]);
}

// activate one r-slice (4 elems = 2 half2 words/gate), all in half2 domain.
// i/f/o accs pre-scaled by 0.5 (sigmoid = 0.5*tanh+0.5). 10 MUFU per call.
__device__ __forceinline__ void act_r(const uint32_t acc[4][2], uint32_t cst[2], uint32_t hw[2]) {
    const __half2 hf = __float2half2_rn(0.5f);
    #pragma unroll
    for (int w = 0; w < 2; ++w) {
        __half2 it = u2h(tanh2u(acc[0][w]));
        __half2 ft = u2h(tanh2u(acc[1][w]));
        __half2 gt = u2h(tanh2u(acc[2][w]));
        __half2 ot = u2h(tanh2u(acc[3][w]));
        __half2 is = __hfma2(it, hf, hf);
        __half2 fs = __hfma2(ft, hf, hf);
        __half2 os = __hfma2(ot, hf, hf);
        __half2 c  = __hfma2(fs, u2h(cst[w]), __hmul2(is, gt));
        cst[w] = h2u(c);
        __half2 ct = u2h(tanh2u(h2u(c)));
        hw[w] = h2u(__hmul2(os, ct));
    }
}

// Phase: mma(group GM) into accM; act(accA -> h of group GA); stage x(GA,t+1).
template <int GM, int GA>
__device__ __forceinline__ void phase_fn(uint32_t* __restrict__ Xs, uint32_t* __restrict__ Hs,
                                         uint32_t (&accM)[2][4][2], uint32_t (&accA)[2][4][2],
                                         uint32_t (&cst)[2][2], float4& xr,
                                         const float* __restrict__ xga, int t, int lane,
                                         int xoff0, int xoff1, int hoff0, int hoff1,
                                         const uint32_t (&bfr)[4][6][2],
                                         const uint32_t (&biasw)[4]) {
    const uint32_t* Xm = Xs + GM * 512;
    const uint32_t* Hm = Hs + GM * 1024;

    #pragma unroll
    for (int r = 0; r < 2; ++r)
        #pragma unroll
        for (int g = 0; g < 4; ++g) {
            accM[r][g][0] = biasw[g];
            accM[r][g][1] = biasw[g];
        }

    uint32_t hw0[2], hw1[2];

    // x-part of K (q=0..1) interleaved with act r=0
    frag_mma(accM[0], Xm + 0,   lane, bfr, 0);
    frag_mma(accM[1], Xm + 128, lane, bfr, 0);
    act_r(accA[0], cst[0], hw0);
    frag_mma(accM[0], Xm + 256, lane, bfr, 1);
    frag_mma(accM[1], Xm + 384, lane, bfr, 1);

    // h-part q=2..3 interleaved with act r=1
    frag_mma(accM[0], Hm + 0,   lane, bfr, 2);
    frag_mma(accM[1], Hm + 128, lane, bfr, 2);
    act_r(accA[1], cst[1], hw1);
    frag_mma(accM[0], Hm + 256, lane, bfr, 3);
    frag_mma(accM[1], Hm + 384, lane, bfr, 3);

    // stage x(GA, t+1) + prefetch x(GA, t+2)
    {
        uint32_t* Xa = Xs + GA * 512;
        Xa[xoff0] = packh2(xr.x, xr.y);
        Xa[xoff1] = packh2(xr.z, xr.w);
        int tt = (t + 2 < T_LEN) ? t + 2 : T_LEN - 1;
        xr = *reinterpret_cast<const float4*>(xga + (size_t)tt * I_SZ);
    }

    frag_mma(accM[0], Hm + 512, lane, bfr, 4);
    frag_mma(accM[1], Hm + 640, lane, bfr, 4);

    // h(GA) writeback: h words ARE the frag-major smem words
    {
        uint32_t* Ha = Hs + GA * 1024;
        *reinterpret_cast<uint2*>(Ha + hoff0) = make_uint2(hw0[0], hw0[1]);
        *reinterpret_cast<uint2*>(Ha + hoff1) = make_uint2(hw1[0], hw1[1]);
    }

    frag_mma(accM[0], Hm + 768, lane, bfr, 5);
    frag_mma(accM[1], Hm + 896, lane, bfr, 5);
}

__global__ __launch_bounds__(NTHREADS, 1)
void lstm_fp16_kernel(const float* __restrict__ x,
                      const float* __restrict__ W_ih,
                      const float* __restrict__ W_hh,
                      const float* __restrict__ b_ih,
                      const float* __restrict__ b_hh,
                      const float* __restrict__ W_fc,
                      const float* __restrict__ b_fc,
                      float* __restrict__ out) {
    __shared__ __align__(16) uint32_t Xs[2 * 512];
    __shared__ __align__(16) uint32_t Hs[2 * 1024];

    const int tid  = threadIdx.x;
    const int warp = tid >> 5;
    const int lane = tid & 31;
    const int row0 = blockIdx.x * M_BLK;
    const int colw = warp * 8;
    const int arl  = lane >> 2;
    const int akl  = lane & 3;

    // ---- B fragments (fp16 half2), i/f/o pre-scaled by 0.5 ----
    uint32_t bfr[4][6][2];
    uint32_t biasw[4];
    {
        const int gc_base = colw + arl;
        #pragma unroll
        for (int g = 0; g < 4; ++g) {
            const int gc = g * 64 + gc_base;
            const float s = (g == 2) ? 1.0f : 0.5f;
            #pragma unroll
            for (int q = 0; q < 6; ++q) {
                const int k0 = q * 16 + 2 * akl;
                float w[4];
                #pragma unroll
                for (int j = 0; j < 4; ++j) {
                    const int k = k0 + ((j < 2) ? j : j + 6);   // k0,k0+1,k0+8,k0+9
                    w[j] = (k < I_SZ) ? W_ih[gc * I_SZ + k] : W_hh[gc * H_SZ + (k - I_SZ)];
                }
                bfr[g][q][0] = packh2(w[0] * s, w[1] * s);
                bfr[g][q][1] = packh2(w[2] * s, w[3] * s);
            }
            const int c0 = g * 64 + colw + 2 * akl;
            biasw[g] = packh2((b_ih[c0] + b_hh[c0]) * s,
                              (b_ih[c0 + 1] + b_hh[c0 + 1]) * s);
        }
    }

    // zero H tiles (h0 = 0)
    for (int i = tid; i < 2 * 1024; i += NTHREADS) Hs[i] = 0u;

    // ---- x staging ownership: float4 per thread per group ----
    const int srow = tid >> 3;
    const int scol = (tid & 7) * 4;
    int xoff0, xoff1;
    {
        const int qx = scol >> 4, rx = srow >> 4;
        const int arls = srow & 7, subx = (srow >> 3) & 1;
        const int p0 = (scol & 15) >> 1;
        const int tg0 = p0 & 3, hfx = p0 >> 2;
        const int word = subx + 2 * hfx;
        xoff0 = (qx * 2 + rx) * 128 + (arls * 4 + tg0) * 4 + word;
        xoff1 = xoff0 + 4;
    }
    const int hoff0 = ((warp >> 1) * 2) * 128 + lane * 4 + 2 * (warp & 1);
    const int hoff1 = hoff0 + 128;

    const float* xga0 = x + ((size_t)(row0 + srow) * T_LEN) * I_SZ + scol;
    const float* xga1 = x + ((size_t)(row0 + 32 + srow) * T_LEN) * I_SZ + scol;

    float4 xr0, xr1;
    {
        float4 v0 = *reinterpret_cast<const float4*>(xga0);
        float4 v1 = *reinterpret_cast<const float4*>(xga1);
        Xs[xoff0]       = packh2(v0.x, v0.y);
        Xs[xoff1]       = packh2(v0.z, v0.w);
        Xs[512 + xoff0] = packh2(v1.x, v1.y);
        Xs[512 + xoff1] = packh2(v1.z, v1.w);
        xr0 = *reinterpret_cast<const float4*>(xga0 + I_SZ);
        xr1 = *reinterpret_cast<const float4*>(xga1 + I_SZ);
    }

    uint32_t acc0[2][4][2], acc1[2][4][2];
    uint32_t cst0[2][2] = {{0u, 0u}, {0u, 0u}};
    uint32_t cst1[2][2] = {{0u, 0u}, {0u, 0u}};

    __syncthreads();

    // prologue: gates(G0, 0) -> acc0
    {
        #pragma unroll
        for (int r = 0; r < 2; ++r)
            #pragma unroll
            for (int g = 0; g < 4; ++g) {
                acc0[r][g][0] = biasw[g];
                acc0[r][g][1] = biasw[g];
            }
        #pragma unroll
        for (int q = 0; q < 2; ++q)
            #pragma unroll
            for (int r = 0; r < 2; ++r)
                frag_mma(acc0[r], Xs + (q * 2 + r) * 128, lane, bfr, q);
        #pragma unroll
        for (int qh = 0; qh < 4; ++qh)
            #pragma unroll
            for (int r = 0; r < 2; ++r)
                frag_mma(acc0[r], Hs + (qh * 2 + r) * 128, lane, bfr, 2 + qh);
    }
    __syncthreads();

    for (int t = 0; t < T_LEN; ++t) {
        phase_fn<1, 0>(Xs, Hs, acc1, acc0, cst0, xr0, xga0, t, lane,
                       xoff0, xoff1, hoff0, hoff1, bfr, biasw);
        __syncthreads();
        phase_fn<0, 1>(Xs, Hs, acc0, acc1, cst1, xr1, xga1, t, lane,
                       xoff0, xoff1, hoff0, hoff1, bfr, biasw);
        __syncthreads();
    }

    // ---- FC epilogue: gather h_T from frag-major fp16 tiles ----
    for (int idx = tid; idx < M_BLK * OUT_SZ; idx += NTHREADS) {
        const int row = idx >> 3;
        const int o   = idx & 7;
        const int g   = row >> 5;
        const int lr  = row & 31;
        const int r   = lr >> 4, arle = lr & 7, sube = (lr >> 3) & 1;
        const uint32_t* Hg = Hs + g * 1024;
        const float* wf = W_fc + o * H_SZ;
        float s = b_fc[o];
        #pragma unroll
        for (int cc = 0; cc < 32; ++cc) {
            const int c  = cc * 2;
            const int qh = c >> 4;
            const int p  = (c & 15) >> 1;
            uint32_t wv = Hg[(qh * 2 + r) * 128 + (arle * 4 + (p & 3)) * 4 + sube + 2 * (p >> 2)];
            __half2 h2 = *reinterpret_cast<__half2*>(&wv);
            float2 f2 = __half22float2(h2);
            s += f2.x * wf[c] + f2.y * wf[c + 1];
        }
        out[(size_t)(row0 + row) * OUT_SZ + o] = s;
    }
}

extern "C" void kernel_launch(void* const* d_in, const int* in_sizes, int n_in,
                              void* d_out, int out_size) {
    const float* x    = (const float*)d_in[0];
    const float* W_ih = (const float*)d_in[1];
    const float* W_hh = (const float*)d_in[2];
    const float* b_ih = (const float*)d_in[3];
    const float* b_hh = (const float*)d_in[4];
    const float* W_fc = (const float*)d_in[5];
    const float* b_fc = (const float*)d_in[6];
    float* out = (float*)d_out;

    lstm_fp16_kernel<<<B_TOT / M_BLK, NTHREADS>>>(x, W_ih, W_hh, b_ih, b_hh, W_fc, b_fc, out);
}